// round 6
// baseline (speedup 1.0000x reference)
#include <cuda_runtime.h>
#include <cuda_fp16.h>
#include <math.h>

#define N_NODES  50000
#define D_FEAT   128
#define N_EDGES  600000
#define MAXNORM  (1.0f - 4e-3f)   // (1 - eps)/sqrt(c), c = 1
#define CAP      128              // bucket capacity per row (max degree ~35)
#define CAP_SH   7

// ---------------------------------------------------------------------------
// Scratch (__device__ globals; allocation-free rule)
// ---------------------------------------------------------------------------
__device__ __half g_tangent[(size_t)N_NODES * D_FEAT]; // fp16 tangent (x*scale)
__device__ int    g_deg[N_NODES];                      // per-row edge count
__device__ int2   g_bucket[(size_t)N_NODES * CAP];     // {col, f32bits(w)}

// ---------------------------------------------------------------------------
// K1: tangent[i] = fp16( x[i] * artanh(min(||x_i||,1-1e-7)) / max(||x_i||,1e-15) )
//     One warp per node (butterfly reduce gives every lane the norm).
//     Lane 0 also zeroes g_deg.
// ---------------------------------------------------------------------------
__global__ void scale_kernel(const float* __restrict__ x, int n_nodes) {
    int gtid = blockIdx.x * blockDim.x + threadIdx.x;
    int warp = gtid >> 5;
    int lane = gtid & 31;
    if (warp >= n_nodes) return;

    float4 v = reinterpret_cast<const float4*>(x)[(size_t)warp * (D_FEAT / 4) + lane];
    float ss = v.x * v.x + v.y * v.y + v.z * v.z + v.w * v.w;
    #pragma unroll
    for (int o = 16; o; o >>= 1) ss += __shfl_xor_sync(0xffffffffu, ss, o);

    float n   = sqrtf(ss);
    float nm  = fmaxf(n, 1e-15f);
    float t   = fminf(nm, 1.0f - 1e-7f);
    float art = 0.5f * (log1pf(t) - log1pf(-t));
    float s   = art / nm;

    // write 4 halfs (8B) per lane: warp covers the 256B fp16 row coalesced
    half2 h0 = __floats2half2_rn(v.x * s, v.y * s);
    half2 h1 = __floats2half2_rn(v.z * s, v.w * s);
    uint2 pk;
    pk.x = *reinterpret_cast<unsigned*>(&h0);
    pk.y = *reinterpret_cast<unsigned*>(&h1);
    reinterpret_cast<uint2*>(g_tangent)[(size_t)warp * (D_FEAT / 4) + lane] = pk;

    if (lane == 0) g_deg[warp] = 0;
}

// ---------------------------------------------------------------------------
// K2: scan-free bucket fill. bucket[r][pos] = {col, w} (8-byte store).
//     (logmap scale is already folded into the fp16 tangent.)
// ---------------------------------------------------------------------------
__global__ void fill_kernel(const int* __restrict__ erow,
                            const int* __restrict__ ecol,
                            const float* __restrict__ ew,
                            int n_edges) {
    int e = blockIdx.x * blockDim.x + threadIdx.x;
    if (e >= n_edges) return;
    int   r = erow[e];
    int   c = ecol[e];
    float w = ew[e];
    int pos = atomicAdd(&g_deg[r], 1);
    if (pos < CAP) {
        int2 pk; pk.x = c; pk.y = __float_as_int(w);
        g_bucket[((size_t)r << CAP_SH) + pos] = pk;
    }
}

// ---------------------------------------------------------------------------
// K3: warp-per-row fp16 gather + fp32 register accumulate + fused expmap0+proj.
//     Each lane owns 4 feature columns; per-edge load is 8B (uint2 of halfs).
//     Dummy (col=0, w=0) padding keeps the inner loop in fixed unroll-4 form.
// ---------------------------------------------------------------------------
__global__ void gather_kernel(float* __restrict__ out, int n_nodes) {
    int gtid = blockIdx.x * blockDim.x + threadIdx.x;
    int warp = gtid >> 5;
    int lane = gtid & 31;
    if (warp >= n_nodes) return;

    int deg = min(g_deg[warp], CAP);
    const int2* bk = g_bucket + ((size_t)warp << CAP_SH);
    const uint2* tb = reinterpret_cast<const uint2*>(g_tangent);

    float4 acc = make_float4(0.f, 0.f, 0.f, 0.f);

    for (int j0 = 0; j0 < deg; j0 += 32) {
        int jk = min(32, deg - j0);
        int2 e = (lane < jk) ? bk[j0 + lane] : make_int2(0, 0);  // w=0.0f dummy
        int kk = (jk + 3) & ~3;
        #pragma unroll 1
        for (int i = 0; i < kk; i += 4) {
            #pragma unroll
            for (int u = 0; u < 4; u++) {
                int   cc = __shfl_sync(0xffffffffu, e.x, i + u);
                float ww = __int_as_float(__shfl_sync(0xffffffffu, e.y, i + u));
                uint2 hv = tb[(size_t)cc * (D_FEAT / 4) + lane];
                float2 f0 = __half22float2(*reinterpret_cast<half2*>(&hv.x));
                float2 f1 = __half22float2(*reinterpret_cast<half2*>(&hv.y));
                acc.x = fmaf(ww, f0.x, acc.x);
                acc.y = fmaf(ww, f0.y, acc.y);
                acc.z = fmaf(ww, f1.x, acc.z);
                acc.w = fmaf(ww, f1.y, acc.w);
            }
        }
    }

    // fused expmap0 + proj: un = max(||u||,1e-15); t = tanh(un);
    //                       f = min(t, MAXNORM) / un
    float ss = acc.x * acc.x + acc.y * acc.y + acc.z * acc.z + acc.w * acc.w;
    #pragma unroll
    for (int o = 16; o; o >>= 1) ss += __shfl_xor_sync(0xffffffffu, ss, o);

    float n  = sqrtf(ss);
    float un = fmaxf(n, 1e-15f);
    float t  = tanhf(un);
    float f  = (t > MAXNORM ? MAXNORM : t) / un;

    acc.x *= f; acc.y *= f; acc.z *= f; acc.w *= f;
    reinterpret_cast<float4*>(out)[(size_t)warp * (D_FEAT / 4) + lane] = acc;
}

// ---------------------------------------------------------------------------
// Launch
// ---------------------------------------------------------------------------
extern "C" void kernel_launch(void* const* d_in, const int* in_sizes, int n_in,
                              void* d_out, int out_size) {
    const float* x    = (const float*)d_in[0];
    const int*   erow = (const int*)d_in[1];
    const int*   ecol = (const int*)d_in[2];
    const float* ew   = (const float*)d_in[3];
    float*       out  = (float*)d_out;

    int n_nodes = in_sizes[0] / D_FEAT;
    int n_edges = in_sizes[3];

    const int T = 256;
    int blkNodeWarp = (n_nodes * 32 + T - 1) / T;  // warp per node
    int blkEdge     = (n_edges + T - 1) / T;       // thread per edge

    scale_kernel<<<blkNodeWarp, T>>>(x, n_nodes);
    fill_kernel<<<blkEdge, T>>>(erow, ecol, ew, n_edges);
    gather_kernel<<<blkNodeWarp, T>>>(out, n_nodes);
}